// round 12
// baseline (speedup 1.0000x reference)
#include <cuda_runtime.h>
#include <cstdint>

// TopK keep: zero all but the K=512 largest entries per 4096-wide row.
// PERSISTENT kernel: 888 CTAs (6/SM) grid-stride over 16384 rows. Each
// iteration prefetches the NEXT row into smem via cp.async.cg while the
// current row (register-resident) runs the select pipeline -- overlapping
// DRAM latency with compute.
//
// Select: 512-bin radix level over [1.0625, 2.125) on raw float bits
// (positive floats: bit order == float order); values >= 2.125 counted in
// registers (warp reduce + leader atomic, no hot-bin ATOMS). Parallel
// suffix scan -> winning bin + rank; atomic append compacts bin (m ~ 1-4);
// warp-0 bitonic resolves exact K-th key. Guards keep it exact for ANY
// input: tot<K / nhigh>=K / m>512 -> 32-step binary-search fallback;
// need != n_eq -> stable lowest-index tie ranking.

#define D_DIM   4096
#define K_KEEP  512
#define NT      256
#define PT      16
#define NW      8
#define T0F     1.0625f
#define HIF     2.125f
#define BOFF    0xFE20u      // f2u(1.0625) >> 14
#define NBIN    512
#define CMAX    512
#define NCTA    888          // 148 SMs * 6 CTAs

__device__ __forceinline__ unsigned f2k(float f) {
    unsigned u = __float_as_uint(f);
    return u ^ ((unsigned)((int)u >> 31) | 0x80000000u);
}
__device__ __forceinline__ float k2f(unsigned k) {
    return __uint_as_float(k ^ ((unsigned)((int)(~k) >> 31) | 0x80000000u));
}

__global__ __launch_bounds__(NT, 6)
void topk_keep_kernel(const float* __restrict__ x, float* __restrict__ out, int rows)
{
    __shared__ __align__(16) float    fbuf[D_DIM];   // 16KB row staging
    __shared__ __align__(16) unsigned hist[NBIN];    // 2KB
    __shared__ __align__(16) unsigned cbuf[CMAX];    // 2KB
    __shared__ unsigned wsum[NW];
    __shared__ unsigned cnt, snhigh, selb, selk, stot, sT, sneed, sneq;

    const int tid  = threadIdx.x;
    const int lane = tid & 31;
    const int warp = tid >> 5;
    const unsigned sbase = (unsigned)__cvta_generic_to_shared(fbuf);

    // issue 4x16B cp.async per thread = one 16KB row
    #define PREFETCH_ROW(srcp) do {                                         \
        const char* _g = (const char*)(srcp);                                \
        _Pragma("unroll")                                                    \
        for (int _r = 0; _r < 4; ++_r) {                                     \
            unsigned _off = (unsigned)(_r * 4096 + tid * 16);                \
            asm volatile("cp.async.cg.shared.global [%0], [%1], 16;"         \
                         :: "r"(sbase + _off), "l"(_g + _off));              \
        }                                                                    \
        asm volatile("cp.async.commit_group;" ::: "memory");                 \
    } while (0)

    int row = blockIdx.x;
    if (row < rows) PREFETCH_ROW(x + (size_t)row * D_DIM);

    for (; row < rows; row += gridDim.x) {
        asm volatile("cp.async.wait_group 0;" ::: "memory");
        __syncthreads();                                   // row data visible to all

        // ---- copy row slice to registers (tid owns elements tid*16..+15) ----
        float f0[PT];
        {
            const float4* sb = reinterpret_cast<const float4*>(fbuf) + tid * 4;
            float4 v0 = sb[0], v1 = sb[1], v2 = sb[2], v3 = sb[3];
            f0[0]=v0.x;  f0[1]=v0.y;  f0[2]=v0.z;  f0[3]=v0.w;
            f0[4]=v1.x;  f0[5]=v1.y;  f0[6]=v1.z;  f0[7]=v1.w;
            f0[8]=v2.x;  f0[9]=v2.y;  f0[10]=v2.z; f0[11]=v2.w;
            f0[12]=v3.x; f0[13]=v3.y; f0[14]=v3.z; f0[15]=v3.w;
        }
        if (tid < NBIN / 4)
            reinterpret_cast<uint4*>(hist)[tid] = make_uint4(0u,0u,0u,0u);
        if (tid == 0) { cnt = 0u; snhigh = 0u; }
        __syncthreads();                                   // fbuf reads done + hist zeroed

        // ---- overlap: start fetching the NEXT row now ----
        {
            int nrow = row + (int)gridDim.x;
            if (nrow < rows) PREFETCH_ROW(x + (size_t)nrow * D_DIM);
        }

        // ---- histogram [T0F,HIF) + register count of highs ----
        unsigned ch = 0;
#pragma unroll
        for (int i = 0; i < PT; ++i) {
            float f = f0[i];
            if (f >= T0F) {
                if (f < HIF)
                    atomicAdd(&hist[(__float_as_uint(f) >> 14) - BOFF], 1u);
                else
                    ++ch;
            }
        }
        ch = __reduce_add_sync(0xffffffffu, ch);
        if (lane == 0 && ch) atomicAdd(&snhigh, ch);
        __syncthreads();

        // ---- parallel suffix scan over 512 bins (2/thread), baseline nhigh ----
        const unsigned nhigh = snhigh;
        unsigned kth = K_KEEP;
        unsigned tot;
        {
            uint2 a = reinterpret_cast<const uint2*>(hist)[tid];
            unsigned ct = a.x + a.y;
            unsigned s = ct;
#pragma unroll
            for (int o = 1; o < 32; o <<= 1) {
                unsigned v = __shfl_down_sync(0xffffffffu, s, o);
                if (lane + o < 32) s += v;
            }
            if (lane == 0) wsum[warp] = s;
            __syncthreads();
            unsigned addh = nhigh; tot = nhigh;
#pragma unroll
            for (int w = 0; w < NW; ++w) {
                unsigned v = wsum[w];
                tot += v;
                if (w > warp) addh += v;
            }
            if (tot >= K_KEEP && nhigh < K_KEEP) {
                unsigned beyond = (s - ct) + addh;
                if (beyond < kth && beyond + ct >= kth) {
                    unsigned rb = beyond;
                    if (rb < kth && rb + a.y >= kth) { selb = (unsigned)(tid*2+1); selk = kth - rb; }
                    rb += a.y;
                    if (rb < kth && rb + a.x >= kth) { selb = (unsigned)(tid*2);   selk = kth - rb; }
                }
            }
            __syncthreads();
        }

        bool fb = (tot < K_KEEP) || (nhigh >= K_KEEP);
        unsigned binKey = 0, kk = 0, m = 0;
        if (!fb) {
            binKey = BOFF + selb;
            kk     = selk;
            // ---- compact winning-bin values (bounded append) ----
#pragma unroll
            for (int i = 0; i < PT; ++i) {
                unsigned u = __float_as_uint(f0[i]);
                if ((u >> 14) == binKey) {
                    unsigned idx = atomicAdd(&cnt, 1u);
                    if (idx < CMAX) cbuf[idx] = u;
                }
            }
            __syncthreads();
            m = cnt;
            fb = (m > CMAX);
        }

        if (fb) {
            // ---- exact fallback: 32-step binary search in key space ----
            unsigned k0[PT];
#pragma unroll
            for (int i = 0; i < PT; ++i) k0[i] = f2k(f0[i]);
            unsigned lo = 0u, hi = 0xFFFFFFFFu;
#pragma unroll 1
            while (lo < hi) {
                unsigned mid = lo + ((hi - lo) >> 1) + ((hi - lo) & 1u);
                unsigned c = 0;
#pragma unroll
                for (int i = 0; i < PT; ++i) c += (k0[i] >= mid) ? 1u : 0u;
                c = __reduce_add_sync(0xffffffffu, c);
                if (lane == 0) wsum[warp] = c;
                __syncthreads();
                if (warp == 0) {
                    unsigned v = (lane < NW) ? wsum[lane] : 0u;
#pragma unroll
                    for (int o = 4; o > 0; o >>= 1) v += __shfl_down_sync(0xffffffffu, v, o);
                    if (lane == 0) stot = v;
                }
                __syncthreads();
                if (stot >= K_KEEP) lo = mid; else hi = mid - 1u;
            }
            const unsigned T = lo;
            unsigned cg = 0, ceq = 0;
#pragma unroll
            for (int i = 0; i < PT; ++i) {
                cg  += (k0[i] > T)  ? 1u : 0u;
                ceq += (k0[i] == T) ? 1u : 0u;
            }
            {
                unsigned c = __reduce_add_sync(0xffffffffu, cg);
                if (lane == 0) wsum[warp] = c;
                __syncthreads();
                if (warp == 0) {
                    unsigned v = (lane < NW) ? wsum[lane] : 0u;
#pragma unroll
                    for (int o = 4; o > 0; o >>= 1) v += __shfl_down_sync(0xffffffffu, v, o);
                    if (lane == 0) stot = v;
                }
                __syncthreads();
            }
            const unsigned need = K_KEEP - stot;
            __syncthreads();
            unsigned p = ceq;
#pragma unroll
            for (int o = 1; o < 32; o <<= 1) {
                unsigned v = __shfl_up_sync(0xffffffffu, p, o);
                if (lane >= o) p += v;
            }
            if (lane == 31) wsum[warp] = p;
            __syncthreads();
            unsigned woff = 0;
#pragma unroll
            for (int w = 0; w < NW; ++w) if (w < warp) woff += wsum[w];
            unsigned rank = woff + p - ceq;
            float4* outr = reinterpret_cast<float4*>(out + (size_t)row * D_DIM) + tid * 4;
#pragma unroll
            for (int j = 0; j < 4; ++j) {
                float r[4];
#pragma unroll
                for (int c2 = 0; c2 < 4; ++c2) {
                    unsigned k = k0[j * 4 + c2];
                    bool eq = (k == T);
                    bool keep = (k > T) || (eq && (rank < need));
                    r[c2] = keep ? k2f(k) : 0.0f;
                    rank += eq ? 1u : 0u;
                }
                __stcs(outr + j, make_float4(r[0], r[1], r[2], r[3]));
            }
            __syncthreads();   // protect wsum/shared state before next iteration
            continue;
        }

        // ---- warp-0 exact select within bin ----
        if (warp == 0) {
            if (m <= 32u) {
                unsigned orig = (lane < (int)m) ? cbuf[lane] : 0u;
                unsigned v = orig;
#pragma unroll
                for (int k = 2; k <= 32; k <<= 1) {
#pragma unroll
                    for (int j = k >> 1; j > 0; j >>= 1) {
                        unsigned o = __shfl_xor_sync(0xffffffffu, v, j);
                        bool dirUp   = ((lane & k) == 0);
                        bool takeMax = ((lane & j) != 0);
                        unsigned mn = umin(v, o), mx = umax(v, o);
                        v = (dirUp == takeMax) ? mx : mn;
                    }
                }
                unsigned T = __shfl_sync(0xffffffffu, v, 32 - (int)kk);
                unsigned cg = __reduce_add_sync(0xffffffffu, (orig > T)  ? 1u : 0u);
                unsigned ce = __reduce_add_sync(0xffffffffu, (orig == T) ? 1u : 0u);
                if (lane == 0) { sT = T; sneed = kk - cg; sneq = ce; }
            } else {
                unsigned lo = binKey << 14, hi = (binKey << 14) | 0x3FFFu;
                unsigned vv[16];   // m <= CMAX = 512 -> 16/lane
#pragma unroll
                for (int t = 0; t < 16; ++t) {
                    unsigned j = (unsigned)lane + t * 32u;
                    vv[t] = (j < m) ? cbuf[j] : 0u;
                }
#pragma unroll 1
                while (lo < hi) {
                    unsigned mid = lo + ((hi - lo) >> 1) + ((hi - lo) & 1u);
                    unsigned c = 0;
#pragma unroll
                    for (int t = 0; t < 16; ++t) c += (vv[t] >= mid) ? 1u : 0u;
                    c = __reduce_add_sync(0xffffffffu, c);
                    if (c >= kk) lo = mid; else hi = mid - 1u;
                }
                unsigned cg = 0, ce = 0;
#pragma unroll
                for (int t = 0; t < 16; ++t) {
                    cg += (vv[t] > lo)  ? 1u : 0u;
                    ce += (vv[t] == lo) ? 1u : 0u;
                }
                cg = __reduce_add_sync(0xffffffffu, cg);
                ce = __reduce_add_sync(0xffffffffu, ce);
                if (lane == 0) { sT = lo; sneed = kk - cg; sneq = ce; }
            }
        }
        __syncthreads();

        const unsigned need = sneed;
        const unsigned neq  = sneq;
        const float    Tf   = __uint_as_float(sT);

        float4* outr = reinterpret_cast<float4*>(out + (size_t)row * D_DIM) + tid * 4;
        if (need == neq) {
            // ---- fast emit: keep everything >= Tf ----
#pragma unroll
            for (int j = 0; j < 4; ++j) {
                float4 o;
                o.x = (f0[j*4+0] >= Tf) ? f0[j*4+0] : 0.0f;
                o.y = (f0[j*4+1] >= Tf) ? f0[j*4+1] : 0.0f;
                o.z = (f0[j*4+2] >= Tf) ? f0[j*4+2] : 0.0f;
                o.w = (f0[j*4+3] >= Tf) ? f0[j*4+3] : 0.0f;
                __stcs(outr + j, o);
            }
        } else {
            // ---- rare tie path: stable rank, lowest index first ----
            unsigned ceq = 0;
#pragma unroll
            for (int i = 0; i < PT; ++i) ceq += (f0[i] == Tf) ? 1u : 0u;
            unsigned p = ceq;
#pragma unroll
            for (int o = 1; o < 32; o <<= 1) {
                unsigned v = __shfl_up_sync(0xffffffffu, p, o);
                if (lane >= o) p += v;
            }
            if (lane == 31) wsum[warp] = p;
            __syncthreads();
            unsigned woff = 0;
#pragma unroll
            for (int w = 0; w < NW; ++w) if (w < warp) woff += wsum[w];
            unsigned rank = woff + p - ceq;
#pragma unroll
            for (int j = 0; j < 4; ++j) {
                float r[4];
#pragma unroll
                for (int c = 0; c < 4; ++c) {
                    float f = f0[j * 4 + c];
                    bool eq = (f == Tf);
                    bool keep = (f > Tf) || (eq && (rank < need));
                    r[c] = keep ? f : 0.0f;
                    rank += eq ? 1u : 0u;
                }
                __stcs(outr + j, make_float4(r[0], r[1], r[2], r[3]));
            }
            __syncthreads();   // protect wsum before next iteration
        }
    }
    #undef PREFETCH_ROW
}

extern "C" void kernel_launch(void* const* d_in, const int* in_sizes, int n_in,
                              void* d_out, int out_size) {
    const float* x = (const float*)d_in[0];
    float* out = (float*)d_out;
    int rows = out_size / D_DIM;   // 16384
    int grid = rows < NCTA ? rows : NCTA;
    topk_keep_kernel<<<grid, NT>>>(x, out, rows);
}

// round 13
// speedup vs baseline: 1.4160x; 1.4160x over previous
#include <cuda_runtime.h>
#include <cstdint>

// TopK keep: zero all but the K=512 largest entries per 4096-wide row.
// One CTA (256 thr) per row. LOW-REGISTER design: the row is NOT cached in
// registers; compact/emit phases re-read it from L2 (rows stay L2-resident,
// ~28MB/wave << 126MB). Volatile asm loads prevent ptxas from caching the
// row into registers; __launch_bounds__(256,8) -> 2048 threads/SM.
//
// Select: 512-bin radix over [1.0625, 2.125) on raw float bits (positive
// floats: bit order == float order); x >= 2.125 counted in registers (warp
// reduce + leader atomic, no hot-bin ATOMS). Parallel suffix scan -> winning
// bin + rank; atomic append compacts bin (m ~ 1-4); warp-0 bitonic resolves
// the exact K-th key. Exactness guards: tot<K / nhigh>=K / m>CMAX -> exact
// binary-search fallback (re-reads row per probe; ~never taken); m>32 ->
// smem-loop search; need!=n_eq -> stable lowest-index tie ranking.

#define D_DIM   4096
#define K_KEEP  512
#define NT      256
#define NW      8
#define T0F     1.0625f
#define HIF     2.125f
#define BOFF    0xFE20u      // f2u(1.0625) >> 14
#define NBIN    512          // (f2u(2.125)>>14) - BOFF == 512 exactly
#define CMAX    512

__device__ __forceinline__ unsigned f2k(float f) {
    unsigned u = __float_as_uint(f);
    return u ^ ((unsigned)((int)u >> 31) | 0x80000000u);
}
__device__ __forceinline__ float k2f(unsigned k) {
    return __uint_as_float(k ^ ((unsigned)((int)(~k) >> 31) | 0x80000000u));
}

// volatile vector load: forces an actual LDG each time (no reg caching)
__device__ __forceinline__ float4 ldg4v(const float4* p) {
    float4 v;
    asm volatile("ld.global.nc.v4.f32 {%0,%1,%2,%3}, [%4];"
                 : "=f"(v.x), "=f"(v.y), "=f"(v.z), "=f"(v.w) : "l"(p));
    return v;
}

__global__ __launch_bounds__(NT, 8)
void topk_keep_kernel(const float* __restrict__ x, float* __restrict__ out)
{
    __shared__ __align__(16) unsigned hist[NBIN];   // 2KB
    __shared__ __align__(16) unsigned cbuf[CMAX];   // 2KB
    __shared__ unsigned wsum[NW];
    __shared__ unsigned cnt, snhigh, selb, selk, stot, sT, sneed, sneq;

    const int tid  = threadIdx.x;
    const int lane = tid & 31;
    const int warp = tid >> 5;
    const size_t row = (size_t)blockIdx.x * D_DIM;
    const float4* xr = reinterpret_cast<const float4*>(x + row) + tid * 4;
    float4* outr = reinterpret_cast<float4*>(out + row) + tid * 4;

    if (tid < NBIN / 4)
        reinterpret_cast<uint4*>(hist)[tid] = make_uint4(0u,0u,0u,0u);
    if (tid == 0) { cnt = 0u; snhigh = 0u; }
    __syncthreads();                                           // S1

    // ---- pass 1: load row, histogram [T0F,HIF), count highs in regs ----
    unsigned ch = 0;
#pragma unroll
    for (int j = 0; j < 4; ++j) {
        float4 v = xr[j];
        float ff[4] = {v.x, v.y, v.z, v.w};
#pragma unroll
        for (int c = 0; c < 4; ++c) {
            float f = ff[c];
            if (f >= T0F) {
                if (f < HIF)
                    atomicAdd(&hist[(__float_as_uint(f) >> 14) - BOFF], 1u);
                else
                    ++ch;
            }
        }
    }
    ch = __reduce_add_sync(0xffffffffu, ch);
    if (lane == 0 && ch) atomicAdd(&snhigh, ch);
    __syncthreads();                                           // S2

    // ---- parallel suffix scan over 512 bins (2/thread), baseline nhigh ----
    const unsigned nhigh = snhigh;
    unsigned kth = K_KEEP;
    unsigned tot;
    {
        uint2 a = reinterpret_cast<const uint2*>(hist)[tid];
        unsigned ct = a.x + a.y;
        unsigned s = ct;
#pragma unroll
        for (int o = 1; o < 32; o <<= 1) {
            unsigned v = __shfl_down_sync(0xffffffffu, s, o);
            if (lane + o < 32) s += v;
        }
        if (lane == 0) wsum[warp] = s;
        __syncthreads();                                       // S3
        unsigned addh = nhigh; tot = nhigh;
#pragma unroll
        for (int w = 0; w < NW; ++w) {
            unsigned v = wsum[w];
            tot += v;
            if (w > warp) addh += v;
        }
        if (tot >= K_KEEP && nhigh < K_KEEP) {
            unsigned beyond = (s - ct) + addh;
            if (beyond < kth && beyond + ct >= kth) {
                unsigned rb = beyond;
                if (rb < kth && rb + a.y >= kth) { selb = (unsigned)(tid*2+1); selk = kth - rb; }
                rb += a.y;
                if (rb < kth && rb + a.x >= kth) { selb = (unsigned)(tid*2);   selk = kth - rb; }
            }
        }
        __syncthreads();                                       // S4
    }

    bool fb = (tot < K_KEEP) || (nhigh >= K_KEEP);
    unsigned binKey = 0, kk = 0, m = 0;
    if (!fb) {
        binKey = BOFF + selb;
        kk     = selk;
        // ---- pass 2: re-read row (L2 hit), compact winning-bin values ----
#pragma unroll
        for (int j = 0; j < 4; ++j) {
            float4 v = ldg4v(xr + j);
            unsigned uu[4] = {__float_as_uint(v.x), __float_as_uint(v.y),
                              __float_as_uint(v.z), __float_as_uint(v.w)};
#pragma unroll
            for (int c = 0; c < 4; ++c) {
                if ((uu[c] >> 14) == binKey) {
                    unsigned idx = atomicAdd(&cnt, 1u);
                    if (idx < CMAX) cbuf[idx] = uu[c];
                }
            }
        }
        __syncthreads();                                       // S5
        m = cnt;
        fb = (m > CMAX);
    }

    if (fb) {
        // ==== exact fallback (essentially never taken; re-reads per probe) ====
        unsigned lo = 0u, hi = 0xFFFFFFFFu;
#pragma unroll 1
        while (lo < hi) {
            unsigned mid = lo + ((hi - lo) >> 1) + ((hi - lo) & 1u);
            unsigned c = 0;
#pragma unroll 1
            for (int j = 0; j < 4; ++j) {
                float4 v = ldg4v(xr + j);
                c += (f2k(v.x) >= mid) ? 1u : 0u;
                c += (f2k(v.y) >= mid) ? 1u : 0u;
                c += (f2k(v.z) >= mid) ? 1u : 0u;
                c += (f2k(v.w) >= mid) ? 1u : 0u;
            }
            c = __reduce_add_sync(0xffffffffu, c);
            if (lane == 0) wsum[warp] = c;
            __syncthreads();
            if (warp == 0) {
                unsigned v = (lane < NW) ? wsum[lane] : 0u;
#pragma unroll
                for (int o = 4; o > 0; o >>= 1) v += __shfl_down_sync(0xffffffffu, v, o);
                if (lane == 0) stot = v;
            }
            __syncthreads();
            if (stot >= K_KEEP) lo = mid; else hi = mid - 1u;
        }
        const unsigned T = lo;
        unsigned cg = 0, ceq = 0;
#pragma unroll 1
        for (int j = 0; j < 4; ++j) {
            float4 v = ldg4v(xr + j);
            unsigned k4[4] = {f2k(v.x), f2k(v.y), f2k(v.z), f2k(v.w)};
#pragma unroll
            for (int c = 0; c < 4; ++c) {
                cg  += (k4[c] > T)  ? 1u : 0u;
                ceq += (k4[c] == T) ? 1u : 0u;
            }
        }
        {
            unsigned c = __reduce_add_sync(0xffffffffu, cg);
            if (lane == 0) wsum[warp] = c;
            __syncthreads();
            if (warp == 0) {
                unsigned v = (lane < NW) ? wsum[lane] : 0u;
#pragma unroll
                for (int o = 4; o > 0; o >>= 1) v += __shfl_down_sync(0xffffffffu, v, o);
                if (lane == 0) stot = v;
            }
            __syncthreads();
        }
        const unsigned need = K_KEEP - stot;
        __syncthreads();
        unsigned p = ceq;
#pragma unroll
        for (int o = 1; o < 32; o <<= 1) {
            unsigned v = __shfl_up_sync(0xffffffffu, p, o);
            if (lane >= o) p += v;
        }
        if (lane == 31) wsum[warp] = p;
        __syncthreads();
        unsigned woff = 0;
#pragma unroll
        for (int w = 0; w < NW; ++w) if (w < warp) woff += wsum[w];
        unsigned rank = woff + p - ceq;
#pragma unroll 1
        for (int j = 0; j < 4; ++j) {
            float4 v = ldg4v(xr + j);
            unsigned k4[4] = {f2k(v.x), f2k(v.y), f2k(v.z), f2k(v.w)};
            float r[4];
#pragma unroll
            for (int c = 0; c < 4; ++c) {
                bool eq = (k4[c] == T);
                bool keep = (k4[c] > T) || (eq && (rank < need));
                r[c] = keep ? k2f(k4[c]) : 0.0f;
                rank += eq ? 1u : 0u;
            }
            __stcs(outr + j, make_float4(r[0], r[1], r[2], r[3]));
        }
        return;
    }

    // ---- warp-0 exact select within bin ----
    if (warp == 0) {
        if (m <= 32u) {
            // bitonic sort ascending; sentinels (0) sink to low lanes
            unsigned orig = (lane < (int)m) ? cbuf[lane] : 0u;
            unsigned v = orig;
#pragma unroll
            for (int k = 2; k <= 32; k <<= 1) {
#pragma unroll
                for (int j = k >> 1; j > 0; j >>= 1) {
                    unsigned o = __shfl_xor_sync(0xffffffffu, v, j);
                    bool dirUp   = ((lane & k) == 0);
                    bool takeMax = ((lane & j) != 0);
                    unsigned mn = umin(v, o), mx = umax(v, o);
                    v = (dirUp == takeMax) ? mx : mn;
                }
            }
            unsigned T = __shfl_sync(0xffffffffu, v, 32 - (int)kk);
            unsigned cg = __reduce_add_sync(0xffffffffu, (orig > T)  ? 1u : 0u);
            unsigned ce = __reduce_add_sync(0xffffffffu, (orig == T) ? 1u : 0u);
            if (lane == 0) { sT = T; sneed = kk - cg; sneq = ce; }
        } else {
            // rare: 14-bit binary search looping over cbuf in smem
            unsigned lo = binKey << 14, hi = (binKey << 14) | 0x3FFFu;
#pragma unroll 1
            while (lo < hi) {
                unsigned mid = lo + ((hi - lo) >> 1) + ((hi - lo) & 1u);
                unsigned c = 0;
                for (unsigned j = lane; j < m; j += 32u) c += (cbuf[j] >= mid) ? 1u : 0u;
                c = __reduce_add_sync(0xffffffffu, c);
                if (c >= kk) lo = mid; else hi = mid - 1u;
            }
            unsigned cg = 0, ce = 0;
            for (unsigned j = lane; j < m; j += 32u) {
                unsigned v = cbuf[j];
                cg += (v > lo)  ? 1u : 0u;
                ce += (v == lo) ? 1u : 0u;
            }
            cg = __reduce_add_sync(0xffffffffu, cg);
            ce = __reduce_add_sync(0xffffffffu, ce);
            if (lane == 0) { sT = lo; sneed = kk - cg; sneq = ce; }
        }
    }
    __syncthreads();                                           // S6

    const unsigned need = sneed;
    const unsigned neq  = sneq;
    const float    Tf   = __uint_as_float(sT);   // positive float

    if (need == neq) {
        // ---- pass 3 (fast): re-read row from L2, emit thresholded ----
#pragma unroll
        for (int j = 0; j < 4; ++j) {
            float4 v = ldg4v(xr + j);
            float4 o;
            o.x = (v.x >= Tf) ? v.x : 0.0f;
            o.y = (v.y >= Tf) ? v.y : 0.0f;
            o.z = (v.z >= Tf) ? v.z : 0.0f;
            o.w = (v.w >= Tf) ? v.w : 0.0f;
            __stcs(outr + j, o);
        }
        return;
    }

    // ---- rare tie path: stable rank, lowest index first ----
    unsigned ceq = 0;
#pragma unroll 1
    for (int j = 0; j < 4; ++j) {
        float4 v = ldg4v(xr + j);
        ceq += (v.x == Tf) ? 1u : 0u;
        ceq += (v.y == Tf) ? 1u : 0u;
        ceq += (v.z == Tf) ? 1u : 0u;
        ceq += (v.w == Tf) ? 1u : 0u;
    }
    unsigned p = ceq;
#pragma unroll
    for (int o = 1; o < 32; o <<= 1) {
        unsigned v = __shfl_up_sync(0xffffffffu, p, o);
        if (lane >= o) p += v;
    }
    if (lane == 31) wsum[warp] = p;
    __syncthreads();
    unsigned woff = 0;
#pragma unroll
    for (int w = 0; w < NW; ++w) if (w < warp) woff += wsum[w];
    unsigned rank = woff + p - ceq;

#pragma unroll 1
    for (int j = 0; j < 4; ++j) {
        float4 v = ldg4v(xr + j);
        float ff[4] = {v.x, v.y, v.z, v.w};
        float r[4];
#pragma unroll
        for (int c = 0; c < 4; ++c) {
            float f = ff[c];
            bool eq = (f == Tf);
            bool keep = (f > Tf) || (eq && (rank < need));
            r[c] = keep ? f : 0.0f;
            rank += eq ? 1u : 0u;
        }
        __stcs(outr + j, make_float4(r[0], r[1], r[2], r[3]));
    }
}

extern "C" void kernel_launch(void* const* d_in, const int* in_sizes, int n_in,
                              void* d_out, int out_size) {
    const float* x = (const float*)d_in[0];
    float* out = (float*)d_out;
    int rows = out_size / D_DIM;   // 16384
    topk_keep_kernel<<<rows, NT>>>(x, out);
}

// round 14
// speedup vs baseline: 1.7308x; 1.2223x over previous
#include <cuda_runtime.h>
#include <cstdint>

// TopK keep: zero all but the K=512 largest entries per 4096-wide row.
// One CTA (256 thr) per row, 16 floats/thread register-resident.
//
// Level 1 is ATOMIC-FREE: [1.0625, 2.125) spans exactly 2^23 raw-bit units,
// so t = u - 0x3F880000 classifies candidates and d = t>>20 gives 8 bins,
// accumulated in two 8-bit-packed registers per thread, widened to 16-bit
// fields, warp-reduced (REDUX), combined by warp 0. Values >= 2.125 counted
// in a register (reduced the same way). Level 2: 256-bin smem histogram of
// the winning 2^20 bin (~75 elems -> ~75 spread atomics), parallel suffix
// scan, compact winning 2^12 sub-bin (~1-2 values), warp-0 bitonic -> exact
// K-th key T. Guards: tot<K / nhigh>=K / m>CMAX -> exact binary-search
// fallback; m>32 -> smem-loop search; need!=n_eq -> stable tie ranking.

#define D_DIM   4096
#define K_KEEP  512
#define NT      256
#define PT      16
#define NW      8
#define CBASE   0x3F880000u   // f2u(1.0625)
#define HIF     2.125f
#define CMAX    512

__device__ __forceinline__ unsigned f2k(float f) {
    unsigned u = __float_as_uint(f);
    return u ^ ((unsigned)((int)u >> 31) | 0x80000000u);
}
__device__ __forceinline__ float k2f(unsigned k) {
    return __uint_as_float(k ^ ((unsigned)((int)(~k) >> 31) | 0x80000000u));
}

__global__ __launch_bounds__(NT, 6)
void topk_keep_kernel(const float* __restrict__ x, float* __restrict__ out)
{
    __shared__ __align__(16) unsigned hist[256];    // 1KB (level 2)
    __shared__ __align__(16) unsigned cbuf[CMAX];   // 2KB
    __shared__ unsigned sred[NW * 5];               // per-warp packed sums + ch
    __shared__ unsigned wsum[NW];
    __shared__ unsigned cnt, snhigh, selb, selk, stot, sT, sneed, sneq;

    const int tid  = threadIdx.x;
    const int lane = tid & 31;
    const int warp = tid >> 5;
    const size_t row = (size_t)blockIdx.x * D_DIM;

    // ---- load: 16 floats in registers ----
    const float4* xr = reinterpret_cast<const float4*>(x + row) + tid * 4;
    float f0[PT];
    {
        float4 v0 = xr[0], v1 = xr[1], v2 = xr[2], v3 = xr[3];
        f0[0]=v0.x;  f0[1]=v0.y;  f0[2]=v0.z;  f0[3]=v0.w;
        f0[4]=v1.x;  f0[5]=v1.y;  f0[6]=v1.z;  f0[7]=v1.w;
        f0[8]=v2.x;  f0[9]=v2.y;  f0[10]=v2.z; f0[11]=v2.w;
        f0[12]=v3.x; f0[13]=v3.y; f0[14]=v3.z; f0[15]=v3.w;
    }

    hist[tid] = 0u;                       // level-2 hist zero (covered by S_A/S_B)
    if (tid == 0) cnt = 0u;

    // ---- level 1: register-packed 8-bin count + high count (no atomics) ----
    unsigned accA = 0u, accB = 0u, ch = 0u;
#pragma unroll
    for (int i = 0; i < PT; ++i) {
        unsigned u = __float_as_uint(f0[i]);
        unsigned t = u - CBASE;
        if (t < 0x00800000u) {            // candidate in [1.0625, 2.125)
            unsigned d   = t >> 20;       // 0..7
            unsigned inc = 1u << ((d & 3u) << 3);
            if (d < 4u) accA += inc; else accB += inc;
        } else if (f0[i] >= HIF) {
            ++ch;
        }
    }
    {   // widen 8-bit fields -> 16-bit fields, warp-reduce
        unsigned a0 = accA & 0x00FF00FFu;         // d0 | d2<<16
        unsigned a1 = (accA >> 8) & 0x00FF00FFu;  // d1 | d3<<16
        unsigned b0 = accB & 0x00FF00FFu;         // d4 | d6<<16
        unsigned b1 = (accB >> 8) & 0x00FF00FFu;  // d5 | d7<<16
        a0 = __reduce_add_sync(0xffffffffu, a0);
        a1 = __reduce_add_sync(0xffffffffu, a1);
        b0 = __reduce_add_sync(0xffffffffu, b0);
        b1 = __reduce_add_sync(0xffffffffu, b1);
        ch = __reduce_add_sync(0xffffffffu, ch);
        if (lane == 0) {
            sred[warp*5+0] = a0; sred[warp*5+1] = a1;
            sred[warp*5+2] = b0; sred[warp*5+3] = b1;
            sred[warp*5+4] = ch;
        }
    }
    __syncthreads();                                           // S_A

    // ---- warp 0 combines 8 warps; lane 0 suffix-scans 8 bins ----
    if (warp == 0) {
        unsigned r0=0,r1=0,r2=0,r3=0,r4=0;
        if (lane < NW) {
            r0 = sred[lane*5+0]; r1 = sred[lane*5+1];
            r2 = sred[lane*5+2]; r3 = sred[lane*5+3];
            r4 = sred[lane*5+4];
        }
#pragma unroll
        for (int o = 4; o > 0; o >>= 1) {
            r0 += __shfl_down_sync(0xffffffffu, r0, o);
            r1 += __shfl_down_sync(0xffffffffu, r1, o);
            r2 += __shfl_down_sync(0xffffffffu, r2, o);
            r3 += __shfl_down_sync(0xffffffffu, r3, o);
            r4 += __shfl_down_sync(0xffffffffu, r4, o);
        }
        if (lane == 0) {
            unsigned c0 = r0 & 0xFFFFu, c2 = r0 >> 16;
            unsigned c1 = r1 & 0xFFFFu, c3 = r1 >> 16;
            unsigned c4 = r2 & 0xFFFFu, c6 = r2 >> 16;
            unsigned c5 = r3 & 0xFFFFu, c7 = r3 >> 16;
            unsigned s = r4;              // highs baseline
            unsigned sb = 0xFFFFFFFFu, sk = 0u;
            #define STEP(dd, cc) \
                if (s < K_KEEP && s + (cc) >= K_KEEP) { sb = (dd); sk = K_KEEP - s; } s += (cc);
            STEP(7u, c7) STEP(6u, c6) STEP(5u, c5) STEP(4u, c4)
            STEP(3u, c3) STEP(2u, c2) STEP(1u, c1) STEP(0u, c0)
            #undef STEP
            selb = sb; selk = sk; stot = s; snhigh = r4;
        }
    }
    __syncthreads();                                           // S_B

    const unsigned nhigh = snhigh;
    const unsigned tot   = stot;
    const unsigned b1bin = selb;
    const unsigned kk1   = selk;

    bool fb = (tot < K_KEEP) || (nhigh >= K_KEEP) || (b1bin > 7u);
    unsigned base = 0, sub = 0, kk2 = 0, m = 0;
    if (!fb) {
        base = CBASE + (b1bin << 20);     // winning 2^20 span
        // ---- level 2: 256-bin smem histogram of winning bin (~75 elems) ----
#pragma unroll
        for (int i = 0; i < PT; ++i) {
            unsigned t2 = __float_as_uint(f0[i]) - base;
            if (t2 < 0x00100000u)
                atomicAdd(&hist[t2 >> 12], 1u);
        }
        __syncthreads();                                       // S_C

        // ---- parallel suffix scan over 256 bins (1/thread) ----
        unsigned ct = hist[tid];
        unsigned s = ct;
#pragma unroll
        for (int o = 1; o < 32; o <<= 1) {
            unsigned v = __shfl_down_sync(0xffffffffu, s, o);
            if (lane + o < 32) s += v;
        }
        if (lane == 0) wsum[warp] = s;
        __syncthreads();                                       // S_D
        unsigned addh = 0;
#pragma unroll
        for (int w = 0; w < NW; ++w) if (w > warp) addh += wsum[w];
        unsigned beyond = (s - ct) + addh;
        if (beyond < kk1 && beyond + ct >= kk1) {
            selb = (unsigned)tid;         // winning 2^12 sub-bin
            selk = kk1 - beyond;
        }
        __syncthreads();                                       // S_E
        sub = selb;
        kk2 = selk;

        // ---- compact sub-bin values (~1-2; bounded append) ----
#pragma unroll
        for (int i = 0; i < PT; ++i) {
            unsigned u = __float_as_uint(f0[i]);
            if (((u - base) >> 12) == sub) {
                unsigned idx = atomicAdd(&cnt, 1u);
                if (idx < CMAX) cbuf[idx] = u;
            }
        }
        __syncthreads();                                       // S_F
        m = cnt;
        fb = (m > CMAX);
    }

    if (fb) {
        // ==== exact fallback: 32-step binary search in key space ====
        unsigned k0[PT];
#pragma unroll
        for (int i = 0; i < PT; ++i) k0[i] = f2k(f0[i]);
        unsigned lo = 0u, hi = 0xFFFFFFFFu;
#pragma unroll 1
        while (lo < hi) {
            unsigned mid = lo + ((hi - lo) >> 1) + ((hi - lo) & 1u);
            unsigned c = 0;
#pragma unroll
            for (int i = 0; i < PT; ++i) c += (k0[i] >= mid) ? 1u : 0u;
            c = __reduce_add_sync(0xffffffffu, c);
            if (lane == 0) wsum[warp] = c;
            __syncthreads();
            if (warp == 0) {
                unsigned v = (lane < NW) ? wsum[lane] : 0u;
#pragma unroll
                for (int o = 4; o > 0; o >>= 1) v += __shfl_down_sync(0xffffffffu, v, o);
                if (lane == 0) stot = v;
            }
            __syncthreads();
            if (stot >= K_KEEP) lo = mid; else hi = mid - 1u;
        }
        const unsigned T = lo;
        unsigned cg = 0, ceq = 0;
#pragma unroll
        for (int i = 0; i < PT; ++i) {
            cg  += (k0[i] > T)  ? 1u : 0u;
            ceq += (k0[i] == T) ? 1u : 0u;
        }
        {
            unsigned c = __reduce_add_sync(0xffffffffu, cg);
            if (lane == 0) wsum[warp] = c;
            __syncthreads();
            if (warp == 0) {
                unsigned v = (lane < NW) ? wsum[lane] : 0u;
#pragma unroll
                for (int o = 4; o > 0; o >>= 1) v += __shfl_down_sync(0xffffffffu, v, o);
                if (lane == 0) stot = v;
            }
            __syncthreads();
        }
        const unsigned need = K_KEEP - stot;
        __syncthreads();
        unsigned p = ceq;
#pragma unroll
        for (int o = 1; o < 32; o <<= 1) {
            unsigned v = __shfl_up_sync(0xffffffffu, p, o);
            if (lane >= o) p += v;
        }
        if (lane == 31) wsum[warp] = p;
        __syncthreads();
        unsigned woff = 0;
#pragma unroll
        for (int w = 0; w < NW; ++w) if (w < warp) woff += wsum[w];
        unsigned rank = woff + p - ceq;
        float4* outr = reinterpret_cast<float4*>(out + row) + tid * 4;
#pragma unroll
        for (int j = 0; j < 4; ++j) {
            float r[4];
#pragma unroll
            for (int c2 = 0; c2 < 4; ++c2) {
                unsigned k = k0[j * 4 + c2];
                bool eq = (k == T);
                bool keep = (k > T) || (eq && (rank < need));
                r[c2] = keep ? k2f(k) : 0.0f;
                rank += eq ? 1u : 0u;
            }
            outr[j] = make_float4(r[0], r[1], r[2], r[3]);
        }
        return;
    }

    // ---- warp-0 exact select within 2^12 sub-bin ----
    if (warp == 0) {
        if (m <= 32u) {
            unsigned orig = (lane < (int)m) ? cbuf[lane] : 0u;
            unsigned v = orig;
#pragma unroll
            for (int k = 2; k <= 32; k <<= 1) {
#pragma unroll
                for (int j = k >> 1; j > 0; j >>= 1) {
                    unsigned o = __shfl_xor_sync(0xffffffffu, v, j);
                    bool dirUp   = ((lane & k) == 0);
                    bool takeMax = ((lane & j) != 0);
                    unsigned mn = umin(v, o), mx = umax(v, o);
                    v = (dirUp == takeMax) ? mx : mn;
                }
            }
            unsigned T = __shfl_sync(0xffffffffu, v, 32 - (int)kk2);
            unsigned cg = __reduce_add_sync(0xffffffffu, (orig > T)  ? 1u : 0u);
            unsigned ce = __reduce_add_sync(0xffffffffu, (orig == T) ? 1u : 0u);
            if (lane == 0) { sT = T; sneed = kk2 - cg; sneq = ce; }
        } else {
            // rare: 12-bit binary search looping over cbuf in smem
            unsigned lo = base + (sub << 12), hi = lo | 0xFFFu;
#pragma unroll 1
            while (lo < hi) {
                unsigned mid = lo + ((hi - lo) >> 1) + ((hi - lo) & 1u);
                unsigned c = 0;
                for (unsigned j = lane; j < m; j += 32u) c += (cbuf[j] >= mid) ? 1u : 0u;
                c = __reduce_add_sync(0xffffffffu, c);
                if (c >= kk2) lo = mid; else hi = mid - 1u;
            }
            unsigned cg = 0, ce = 0;
            for (unsigned j = lane; j < m; j += 32u) {
                unsigned v = cbuf[j];
                cg += (v > lo)  ? 1u : 0u;
                ce += (v == lo) ? 1u : 0u;
            }
            cg = __reduce_add_sync(0xffffffffu, cg);
            ce = __reduce_add_sync(0xffffffffu, ce);
            if (lane == 0) { sT = lo; sneed = kk2 - cg; sneq = ce; }
        }
    }
    __syncthreads();                                           // S_G

    const unsigned need = sneed;
    const unsigned neq  = sneq;
    const float    Tf   = __uint_as_float(sT);   // positive float

    float4* outr = reinterpret_cast<float4*>(out + row) + tid * 4;
    if (need == neq) {
        // ---- fast emit: keep everything >= Tf ----
#pragma unroll
        for (int j = 0; j < 4; ++j) {
            float4 o;
            o.x = (f0[j*4+0] >= Tf) ? f0[j*4+0] : 0.0f;
            o.y = (f0[j*4+1] >= Tf) ? f0[j*4+1] : 0.0f;
            o.z = (f0[j*4+2] >= Tf) ? f0[j*4+2] : 0.0f;
            o.w = (f0[j*4+3] >= Tf) ? f0[j*4+3] : 0.0f;
            outr[j] = o;
        }
        return;
    }

    // ---- rare tie path: stable rank, lowest index first ----
    unsigned ceq = 0;
#pragma unroll
    for (int i = 0; i < PT; ++i) ceq += (f0[i] == Tf) ? 1u : 0u;
    unsigned p = ceq;
#pragma unroll
    for (int o = 1; o < 32; o <<= 1) {
        unsigned v = __shfl_up_sync(0xffffffffu, p, o);
        if (lane >= o) p += v;
    }
    if (lane == 31) wsum[warp] = p;
    __syncthreads();
    unsigned woff = 0;
#pragma unroll
    for (int w = 0; w < NW; ++w) if (w < warp) woff += wsum[w];
    unsigned rank = woff + p - ceq;

#pragma unroll
    for (int j = 0; j < 4; ++j) {
        float r[4];
#pragma unroll
        for (int c = 0; c < 4; ++c) {
            float f = f0[j * 4 + c];
            bool eq = (f == Tf);
            bool keep = (f > Tf) || (eq && (rank < need));
            r[c] = keep ? f : 0.0f;
            rank += eq ? 1u : 0u;
        }
        outr[j] = make_float4(r[0], r[1], r[2], r[3]);
    }
}

extern "C" void kernel_launch(void* const* d_in, const int* in_sizes, int n_in,
                              void* d_out, int out_size) {
    const float* x = (const float*)d_in[0];
    float* out = (float*)d_out;
    int rows = out_size / D_DIM;   // 16384
    topk_keep_kernel<<<rows, NT>>>(x, out);
}